// round 1
// baseline (speedup 1.0000x reference)
#include <cuda_runtime.h>
#include <cuda_bf16.h>
#include <cstdint>

// Problem constants
#define BB 64
#define KK 64
#define DD 128
#define HH 128
#define TT 4
#define ROWS (BB*KK)        // 4096
#define EPSLN 1e-5f

#define RELU_FLAG  1
#define ACCUM_FLAG 2

// ---------------- scratch (no allocations allowed) ----------------
__device__ float g_XN [ROWS*DD];
__device__ float g_T1 [ROWS*2*DD];       // reused for width-128 intermediates
__device__ float g_HDS[ROWS*DD];
__device__ float g_A  [TT*ROWS*HH];
__device__ float g_Bm [TT*ROWS*HH];
__device__ float g_S  [TT*ROWS*HH];
__device__ float g_W  [TT*ROWS];
__device__ float g_DI [ROWS*DD];
__device__ float g_CN [ROWS*2*DD];
__device__ float g_H  [ROWS*DD];

// ---------------- LayerNorm, width 128 (one warp per row) ----------------
__global__ void __launch_bounds__(256) ln128_kernel(
    const float* __restrict__ x, const float* __restrict__ g,
    const float* __restrict__ b, float* __restrict__ out)
{
    int lane = threadIdx.x & 31;
    int wid  = threadIdx.x >> 5;
    int row  = blockIdx.x * 8 + wid;
    const float4* x4 = (const float4*)x;
    float4 v = x4[row*32 + lane];
    float s = v.x + v.y + v.z + v.w;
    #pragma unroll
    for (int o = 16; o; o >>= 1) s += __shfl_xor_sync(0xffffffffu, s, o);
    float mu = s * (1.0f/128.0f);
    float dx = v.x-mu, dy = v.y-mu, dz = v.z-mu, dw = v.w-mu;
    float q = dx*dx + dy*dy + dz*dz + dw*dw;
    #pragma unroll
    for (int o = 16; o; o >>= 1) q += __shfl_xor_sync(0xffffffffu, q, o);
    float rs = rsqrtf(q * (1.0f/128.0f) + EPSLN);
    float4 gg = ((const float4*)g)[lane];
    float4 bb = ((const float4*)b)[lane];
    float4 o4;
    o4.x = dx*rs*gg.x + bb.x;
    o4.y = dy*rs*gg.y + bb.y;
    o4.z = dz*rs*gg.z + bb.z;
    o4.w = dw*rs*gg.w + bb.w;
    ((float4*)out)[row*32 + lane] = o4;
}

// ---------------- LayerNorm over concat([hds, di]) width 256 ----------------
__global__ void __launch_bounds__(256) ln256cat_kernel(
    const float* __restrict__ hds, const float* __restrict__ di,
    const float* __restrict__ g, const float* __restrict__ b,
    float* __restrict__ out)
{
    int lane = threadIdx.x & 31;
    int wid  = threadIdx.x >> 5;
    int row  = blockIdx.x * 8 + wid;
    float4 v0 = ((const float4*)hds)[row*32 + lane];
    float4 v1 = ((const float4*)di )[row*32 + lane];
    float s = v0.x+v0.y+v0.z+v0.w + v1.x+v1.y+v1.z+v1.w;
    #pragma unroll
    for (int o = 16; o; o >>= 1) s += __shfl_xor_sync(0xffffffffu, s, o);
    float mu = s * (1.0f/256.0f);
    float a0=v0.x-mu, a1=v0.y-mu, a2=v0.z-mu, a3=v0.w-mu;
    float b0=v1.x-mu, b1=v1.y-mu, b2=v1.z-mu, b3=v1.w-mu;
    float q = a0*a0+a1*a1+a2*a2+a3*a3 + b0*b0+b1*b1+b2*b2+b3*b3;
    #pragma unroll
    for (int o = 16; o; o >>= 1) q += __shfl_xor_sync(0xffffffffu, q, o);
    float rs = rsqrtf(q * (1.0f/256.0f) + EPSLN);
    float4 g0 = ((const float4*)g)[lane];
    float4 g1 = ((const float4*)g)[32 + lane];
    float4 c0 = ((const float4*)b)[lane];
    float4 c1 = ((const float4*)b)[32 + lane];
    float4 o0, o1;
    o0.x = a0*rs*g0.x + c0.x; o0.y = a1*rs*g0.y + c0.y;
    o0.z = a2*rs*g0.z + c0.z; o0.w = a3*rs*g0.w + c0.w;
    o1.x = b0*rs*g1.x + c1.x; o1.y = b1*rs*g1.y + c1.y;
    o1.z = b2*rs*g1.z + c1.z; o1.w = b3*rs*g1.w + c1.w;
    ((float4*)out)[row*64 + lane]      = o0;
    ((float4*)out)[row*64 + 32 + lane] = o1;
}

// ---------------- generic GEMM: out[4096,128] = A[4096,kdim] @ W[kdim,128] ---
// epilogue: (+bias[n]) (+rowscale[row]*rsb[n]) (+resid) (+=out if ACCUM) (relu)
__global__ void __launch_bounds__(256) gemm_n128(
    const float* __restrict__ A, const float* __restrict__ Wm,
    const float* __restrict__ bias, const float* __restrict__ resid,
    const float* __restrict__ rowscale, const float* __restrict__ rsb,
    float* __restrict__ out, int kdim, int flags)
{
    __shared__ float Ws[32*128];
    __shared__ float As[32*32];
    int tid = threadIdx.x;
    int tx = tid & 31, ty = tid >> 5;
    int rowBase = blockIdx.x * 32;
    float acc[4][4] = {};

    for (int k0 = 0; k0 < kdim; k0 += 32) {
        #pragma unroll
        for (int l = 0; l < 4; l++) {
            int q = tid + l*256;
            int r = q >> 5, c = q & 31;
            As[q] = A[(size_t)(rowBase + r)*kdim + k0 + c];
        }
        const float4* Wg = (const float4*)Wm;
        float4* Ws4 = (float4*)Ws;
        #pragma unroll
        for (int l = 0; l < 4; l++) {
            int q = tid + l*256;
            Ws4[q] = Wg[k0*32 + q];
        }
        __syncthreads();
        #pragma unroll 8
        for (int kk = 0; kk < 32; kk++) {
            float4 bv = *(const float4*)&Ws[kk*128 + tx*4];
            #pragma unroll
            for (int r = 0; r < 4; r++) {
                float a = As[(ty + r*8)*32 + kk];
                acc[r][0] += a*bv.x; acc[r][1] += a*bv.y;
                acc[r][2] += a*bv.z; acc[r][3] += a*bv.w;
            }
        }
        __syncthreads();
    }

    int n0 = tx*4;
    float4 bv = bias ? *(const float4*)&bias[n0] : make_float4(0,0,0,0);
    float4 rv = rsb  ? *(const float4*)&rsb[n0]  : make_float4(0,0,0,0);
    #pragma unroll
    for (int r = 0; r < 4; r++) {
        int row = rowBase + ty + r*8;
        float4 v;
        v.x = acc[r][0] + bv.x; v.y = acc[r][1] + bv.y;
        v.z = acc[r][2] + bv.z; v.w = acc[r][3] + bv.w;
        if (rowscale) {
            float w = rowscale[row];
            v.x += w*rv.x; v.y += w*rv.y; v.z += w*rv.z; v.w += w*rv.w;
        }
        if (resid) {
            float4 h4 = *(const float4*)&resid[(size_t)row*128 + n0];
            v.x += h4.x; v.y += h4.y; v.z += h4.z; v.w += h4.w;
        }
        if (flags & ACCUM_FLAG) {
            float4 o4 = *(const float4*)&out[(size_t)row*128 + n0];
            v.x += o4.x; v.y += o4.y; v.z += o4.z; v.w += o4.w;
        }
        if (flags & RELU_FLAG) {
            v.x = fmaxf(v.x,0.f); v.y = fmaxf(v.y,0.f);
            v.z = fmaxf(v.z,0.f); v.w = fmaxf(v.w,0.f);
        }
        *(float4*)&out[(size_t)row*128 + n0] = v;
    }
}

// ---------------- fused inter kernel --------------------------------------
// One block per (b, tau). For each sender i:
//   x1[j,h] = relu(A[b,i,h] + Bm[b,j,h])           (bi1 folded into A)
//   x2[j,n] = relu(sum_h x1[j,h]*wi2[tau][h,n] + bi2[tau][n])
//   acc[j,n] += w[b,i,j,tau] * x2[j,n];  wsum[j] += w
// Outputs S[tau,b,j,n] and Wsum[tau,b,j].
#define X1PAD 132
#define INTER_SMEM_FLOATS (8192 + 8192 + 16384 + 64*X1PAD + 64 + 128)
#define INTER_SMEM_BYTES  (INTER_SMEM_FLOATS * 4)

__global__ void __launch_bounds__(256, 1) inter_kernel(
    const float* __restrict__ gA, const float* __restrict__ gB,
    const float* __restrict__ wi2, const float* __restrict__ bi2,
    const float* __restrict__ ep, const float* __restrict__ et,
    float* __restrict__ gS, float* __restrict__ gW)
{
    extern __shared__ float sm[];
    float* A_s  = sm;               // 64*128
    float* B_s  = A_s + 8192;       // 64*128
    float* W2   = B_s + 8192;       // 128*128
    float* X1   = W2 + 16384;       // 64*132 (padded)
    float* w_s  = X1 + 64*X1PAD;    // 64
    float* bi2s = w_s + 64;         // 128

    int tid = threadIdx.x;
    int b   = blockIdx.x;
    int tau = blockIdx.y;

    const float4* Ag  = (const float4*)(gA  + ((size_t)tau*ROWS + b*64)*128);
    const float4* Bg  = (const float4*)(gB  + ((size_t)tau*ROWS + b*64)*128);
    const float4* W2g = (const float4*)(wi2 + (size_t)tau*16384);
    for (int q = tid; q < 2048; q += 256) { ((float4*)A_s)[q] = Ag[q]; }
    for (int q = tid; q < 2048; q += 256) { ((float4*)B_s)[q] = Bg[q]; }
    for (int q = tid; q < 4096; q += 256) { ((float4*)W2)[q]  = W2g[q]; }
    if (tid < 128) bi2s[tid] = bi2[tau*128 + tid];
    __syncthreads();

    int tx = tid & 15;       // n block: 8 cols
    int ty = tid >> 4;       // j block: 4 rows
    float rbi2[8];
    #pragma unroll
    for (int c = 0; c < 8; c++) rbi2[c] = bi2s[tx*8 + c];

    float acc[4][8] = {};
    float wsum = 0.f;

    const size_t ep_base = (size_t)b*64*64;
    for (int i = 0; i < 64; i++) {
        // build x1 tile and pair weights
        for (int q = tid; q < 8192; q += 256) {
            int j = q >> 7, h = q & 127;
            X1[j*X1PAD + h] = fmaxf(A_s[i*128 + h] + B_s[j*128 + h], 0.f);
        }
        if (tid < 64) {
            size_t idx = ep_base + (size_t)i*64 + tid;
            w_s[tid] = ep[idx] * et[idx*4 + tau];
        }
        __syncthreads();
        if (tid < 64) wsum += w_s[tid];

        float tmp[4][8] = {};
        #pragma unroll 8
        for (int h = 0; h < 128; h++) {
            float4 b0 = *(const float4*)&W2[h*128 + tx*8];
            float4 b1 = *(const float4*)&W2[h*128 + tx*8 + 4];
            #pragma unroll
            for (int r = 0; r < 4; r++) {
                float a = X1[(ty*4 + r)*X1PAD + h];
                tmp[r][0] += a*b0.x; tmp[r][1] += a*b0.y;
                tmp[r][2] += a*b0.z; tmp[r][3] += a*b0.w;
                tmp[r][4] += a*b1.x; tmp[r][5] += a*b1.y;
                tmp[r][6] += a*b1.z; tmp[r][7] += a*b1.w;
            }
        }
        #pragma unroll
        for (int r = 0; r < 4; r++) {
            float wj = w_s[ty*4 + r];
            #pragma unroll
            for (int c = 0; c < 8; c++) {
                acc[r][c] += wj * fmaxf(tmp[r][c] + rbi2[c], 0.f);
            }
        }
        __syncthreads();
    }

    float* So = gS + ((size_t)tau*ROWS + b*64)*128;
    #pragma unroll
    for (int r = 0; r < 4; r++) {
        int j = ty*4 + r;
        float4 v0 = make_float4(acc[r][0], acc[r][1], acc[r][2], acc[r][3]);
        float4 v1 = make_float4(acc[r][4], acc[r][5], acc[r][6], acc[r][7]);
        *(float4*)&So[j*128 + tx*8]     = v0;
        *(float4*)&So[j*128 + tx*8 + 4] = v1;
    }
    if (tid < 64) gW[(size_t)tau*ROWS + b*64 + tid] = wsum;
}

// ---------------- host orchestration --------------------------------------
extern "C" void kernel_launch(void* const* d_in, const int* in_sizes, int n_in,
                              void* d_out, int out_size)
{
    const float* slots = (const float*)d_in[0];
    const float* ep    = (const float*)d_in[1];
    const float* et    = (const float*)d_in[2];
    const float* ls_g  = (const float*)d_in[3];
    const float* ls_b  = (const float*)d_in[4];
    const float* ws1   = (const float*)d_in[5];
    const float* bs1   = (const float*)d_in[6];
    const float* ws2   = (const float*)d_in[7];
    const float* bs2   = (const float*)d_in[8];
    const float* wi1   = (const float*)d_in[9];
    const float* bi1   = (const float*)d_in[10];
    const float* wi2   = (const float*)d_in[11];
    const float* bi2   = (const float*)d_in[12];
    const float* wi3   = (const float*)d_in[13];
    const float* bi3   = (const float*)d_in[14];
    const float* lu_g  = (const float*)d_in[15];
    const float* lu_b  = (const float*)d_in[16];
    const float* wu1   = (const float*)d_in[17];
    const float* bu1   = (const float*)d_in[18];
    const float* wu2   = (const float*)d_in[19];
    const float* bu2   = (const float*)d_in[20];
    float* out = (float*)d_out;

    float *XN, *T1, *HDS, *A, *Bm, *S, *W, *DI, *CN, *H;
    cudaGetSymbolAddress((void**)&XN,  g_XN);
    cudaGetSymbolAddress((void**)&T1,  g_T1);
    cudaGetSymbolAddress((void**)&HDS, g_HDS);
    cudaGetSymbolAddress((void**)&A,   g_A);
    cudaGetSymbolAddress((void**)&Bm,  g_Bm);
    cudaGetSymbolAddress((void**)&S,   g_S);
    cudaGetSymbolAddress((void**)&W,   g_W);
    cudaGetSymbolAddress((void**)&DI,  g_DI);
    cudaGetSymbolAddress((void**)&CN,  g_CN);
    cudaGetSymbolAddress((void**)&H,   g_H);

    cudaFuncSetAttribute(inter_kernel,
                         cudaFuncAttributeMaxDynamicSharedMemorySize,
                         INTER_SMEM_BYTES);

    const float* h = slots;
    for (int it = 0; it < 2; it++) {
        // delta_self path: xn = LN(h); t1 = relu(xn@ws1+bs1); hds = h + t1@ws2+bs2
        ln128_kernel<<<512, 256>>>(h, ls_g, ls_b, XN);
        gemm_n128<<<128, 256>>>(XN, ws1, bs1, nullptr, nullptr, nullptr,
                                T1, 128, RELU_FLAG);
        gemm_n128<<<128, 256>>>(T1, ws2, bs2, h, nullptr, nullptr,
                                HDS, 128, 0);

        // pair-layer-1 factorization: A = h@wi1_top + bi1 ; Bm = h@wi1_bot
        for (int tau = 0; tau < TT; tau++) {
            const float* wtop = wi1 + (size_t)tau*2*DD*HH;
            const float* wbot = wtop + (size_t)DD*HH;
            gemm_n128<<<128, 256>>>(h, wtop, bi1 + tau*HH, nullptr, nullptr,
                                    nullptr, A + (size_t)tau*ROWS*HH, 128, 0);
            gemm_n128<<<128, 256>>>(h, wbot, nullptr, nullptr, nullptr,
                                    nullptr, Bm + (size_t)tau*ROWS*HH, 128, 0);
        }

        // fused per-pair layer-2 + weighted sender reduction
        inter_kernel<<<dim3(BB, TT), 256, INTER_SMEM_BYTES>>>(
            A, Bm, wi2, bi2, ep, et, S, W);

        // delta_inter = sum_tau (S_tau @ wi3[tau] + Wsum_tau * bi3[tau])
        for (int tau = 0; tau < TT; tau++) {
            gemm_n128<<<128, 256>>>(S + (size_t)tau*ROWS*HH,
                                    wi3 + (size_t)tau*HH*DD,
                                    nullptr, nullptr,
                                    W + (size_t)tau*ROWS, bi3 + tau*DD,
                                    DI, 128, tau ? ACCUM_FLAG : 0);
        }

        // update MLP: cn = LN([hds, di]); u = relu(cn@wu1+bu1); h' = h + u@wu2+bu2
        ln256cat_kernel<<<512, 256>>>(HDS, DI, lu_g, lu_b, CN);
        gemm_n128<<<128, 256>>>(CN, wu1, bu1, nullptr, nullptr, nullptr,
                                T1, 256, RELU_FLAG);
        float* hnew = (it == 0) ? H : out;
        gemm_n128<<<128, 256>>>(T1, wu2, bu2, h, nullptr, nullptr,
                                hnew, 128, 0);
        h = H;
    }
}

// round 3
// speedup vs baseline: 5.5088x; 5.5088x over previous
#include <cuda_runtime.h>
#include <cuda_bf16.h>
#include <cstdint>

// Problem constants
#define BB 64
#define KK 64
#define DD 128
#define HH 128
#define TT 4
#define ROWS (BB*KK)        // 4096
#define EPSLN 1e-5f

#define RELU_FLAG  1
#define RS4_FLAG   4

// ---------------- scratch (no allocations allowed) ----------------
__device__ float g_XN [ROWS*DD];
__device__ float g_T1 [ROWS*2*DD];
__device__ float g_HDS[ROWS*DD];
__device__ float g_A  [TT*ROWS*HH];
__device__ float g_Bm [TT*ROWS*HH];
__device__ float g_S  [ROWS*TT*HH];   // [row][tau*128+n]
__device__ float g_W  [ROWS*TT];      // [row][tau]
__device__ float g_DI [ROWS*DD];
__device__ float g_CN [ROWS*2*DD];
__device__ float g_H  [ROWS*DD];

// ---------------- helpers ----------------
__device__ __forceinline__ uint32_t pk2(float lo, float hi){
    __nv_bfloat162 v = __floats2bfloat162_rn(lo, hi);
    return *(uint32_t*)&v;
}
__device__ __forceinline__ uint32_t addrelu2(uint32_t a, uint32_t b){
    __nv_bfloat162 av = *(__nv_bfloat162*)&a;
    __nv_bfloat162 bv = *(__nv_bfloat162*)&b;
    __nv_bfloat162 z  = __float2bfloat162_rn(0.f);
    __nv_bfloat162 r  = __hmax2(__hadd2(av, bv), z);
    return *(uint32_t*)&r;
}
__device__ __forceinline__ void mma16816(float c[4], const uint32_t a[4],
                                         const uint32_t b[2]){
    asm volatile(
        "mma.sync.aligned.m16n8k16.row.col.f32.bf16.bf16.f32 "
        "{%0,%1,%2,%3}, {%4,%5,%6,%7}, {%8,%9}, {%0,%1,%2,%3};\n"
        : "+f"(c[0]), "+f"(c[1]), "+f"(c[2]), "+f"(c[3])
        : "r"(a[0]), "r"(a[1]), "r"(a[2]), "r"(a[3]),
          "r"(b[0]), "r"(b[1]));
}

// ---------------- LayerNorm, width 128 ----------------
__global__ void __launch_bounds__(256) ln128_kernel(
    const float* __restrict__ x, const float* __restrict__ g,
    const float* __restrict__ b, float* __restrict__ out)
{
    int lane = threadIdx.x & 31;
    int wid  = threadIdx.x >> 5;
    int row  = blockIdx.x * 8 + wid;
    float4 v = ((const float4*)x)[row*32 + lane];
    float s = v.x + v.y + v.z + v.w;
    #pragma unroll
    for (int o = 16; o; o >>= 1) s += __shfl_xor_sync(0xffffffffu, s, o);
    float mu = s * (1.0f/128.0f);
    float dx = v.x-mu, dy = v.y-mu, dz = v.z-mu, dw = v.w-mu;
    float q = dx*dx + dy*dy + dz*dz + dw*dw;
    #pragma unroll
    for (int o = 16; o; o >>= 1) q += __shfl_xor_sync(0xffffffffu, q, o);
    float rs = rsqrtf(q * (1.0f/128.0f) + EPSLN);
    float4 gg = ((const float4*)g)[lane];
    float4 bb = ((const float4*)b)[lane];
    float4 o4;
    o4.x = dx*rs*gg.x + bb.x; o4.y = dy*rs*gg.y + bb.y;
    o4.z = dz*rs*gg.z + bb.z; o4.w = dw*rs*gg.w + bb.w;
    ((float4*)out)[row*32 + lane] = o4;
}

// ---------------- LayerNorm over concat([hds, di]) width 256 ----------------
__global__ void __launch_bounds__(256) ln256cat_kernel(
    const float* __restrict__ hds, const float* __restrict__ di,
    const float* __restrict__ g, const float* __restrict__ b,
    float* __restrict__ out)
{
    int lane = threadIdx.x & 31;
    int wid  = threadIdx.x >> 5;
    int row  = blockIdx.x * 8 + wid;
    float4 v0 = ((const float4*)hds)[row*32 + lane];
    float4 v1 = ((const float4*)di )[row*32 + lane];
    float s = v0.x+v0.y+v0.z+v0.w + v1.x+v1.y+v1.z+v1.w;
    #pragma unroll
    for (int o = 16; o; o >>= 1) s += __shfl_xor_sync(0xffffffffu, s, o);
    float mu = s * (1.0f/256.0f);
    float a0=v0.x-mu, a1=v0.y-mu, a2=v0.z-mu, a3=v0.w-mu;
    float b0=v1.x-mu, b1=v1.y-mu, b2=v1.z-mu, b3=v1.w-mu;
    float q = a0*a0+a1*a1+a2*a2+a3*a3 + b0*b0+b1*b1+b2*b2+b3*b3;
    #pragma unroll
    for (int o = 16; o; o >>= 1) q += __shfl_xor_sync(0xffffffffu, q, o);
    float rs = rsqrtf(q * (1.0f/256.0f) + EPSLN);
    float4 g0 = ((const float4*)g)[lane];
    float4 g1 = ((const float4*)g)[32 + lane];
    float4 c0 = ((const float4*)b)[lane];
    float4 c1 = ((const float4*)b)[32 + lane];
    float4 o0, o1;
    o0.x = a0*rs*g0.x + c0.x; o0.y = a1*rs*g0.y + c0.y;
    o0.z = a2*rs*g0.z + c0.z; o0.w = a3*rs*g0.w + c0.w;
    o1.x = b0*rs*g1.x + c1.x; o1.y = b1*rs*g1.y + c1.y;
    o1.z = b2*rs*g1.z + c1.z; o1.w = b3*rs*g1.w + c1.w;
    ((float4*)out)[row*64 + lane]      = o0;
    ((float4*)out)[row*64 + 32 + lane] = o1;
}

// ---------------- GEMM core: out[·,128] tile = A[·,kdim] @ W[kdim,128] ----
__device__ __forceinline__ void gemm_body(
    const float* __restrict__ A, const float* __restrict__ Wm,
    const float* __restrict__ bias, const float* __restrict__ resid,
    const float* __restrict__ rs4, const float* __restrict__ rsb,
    float* __restrict__ out, int kdim, int flags, int rowBase)
{
    __shared__ float Ws[32*128];
    __shared__ float As[32*32];
    int tid = threadIdx.x;
    int tx = tid & 31, ty = tid >> 5;
    float acc[4][4] = {};

    for (int k0 = 0; k0 < kdim; k0 += 32) {
        #pragma unroll
        for (int l = 0; l < 4; l++) {
            int q = tid + l*256;
            int r = q >> 5, c = q & 31;
            As[q] = A[(size_t)(rowBase + r)*kdim + k0 + c];
        }
        const float4* Wg = (const float4*)Wm;
        float4* Ws4 = (float4*)Ws;
        #pragma unroll
        for (int l = 0; l < 4; l++) {
            int q = tid + l*256;
            Ws4[q] = Wg[k0*32 + q];
        }
        __syncthreads();
        #pragma unroll 8
        for (int kk = 0; kk < 32; kk++) {
            float4 bv = *(const float4*)&Ws[kk*128 + tx*4];
            #pragma unroll
            for (int r = 0; r < 4; r++) {
                float a = As[(ty + r*8)*32 + kk];
                acc[r][0] += a*bv.x; acc[r][1] += a*bv.y;
                acc[r][2] += a*bv.z; acc[r][3] += a*bv.w;
            }
        }
        __syncthreads();
    }

    int n0 = tx*4;
    float4 bv = bias ? *(const float4*)&bias[n0] : make_float4(0,0,0,0);
    #pragma unroll
    for (int r = 0; r < 4; r++) {
        int row = rowBase + ty + r*8;
        float4 v;
        v.x = acc[r][0] + bv.x; v.y = acc[r][1] + bv.y;
        v.z = acc[r][2] + bv.z; v.w = acc[r][3] + bv.w;
        if (flags & RS4_FLAG) {
            float4 w4 = *(const float4*)&rs4[row*4];
            #pragma unroll
            for (int t = 0; t < 4; t++) {
                float wt = (t==0)?w4.x:(t==1)?w4.y:(t==2)?w4.z:w4.w;
                float4 rbt = *(const float4*)&rsb[t*128 + n0];
                v.x += wt*rbt.x; v.y += wt*rbt.y; v.z += wt*rbt.z; v.w += wt*rbt.w;
            }
        }
        if (resid) {
            float4 h4 = *(const float4*)&resid[(size_t)row*128 + n0];
            v.x += h4.x; v.y += h4.y; v.z += h4.z; v.w += h4.w;
        }
        if (flags & RELU_FLAG) {
            v.x = fmaxf(v.x,0.f); v.y = fmaxf(v.y,0.f);
            v.z = fmaxf(v.z,0.f); v.w = fmaxf(v.w,0.f);
        }
        *(float4*)&out[(size_t)row*128 + n0] = v;
    }
}

__global__ void __launch_bounds__(256) gemm_n128(
    const float* __restrict__ A, const float* __restrict__ Wm,
    const float* __restrict__ bias, const float* __restrict__ resid,
    const float* __restrict__ rs4, const float* __restrict__ rsb,
    float* __restrict__ out, int kdim, int flags)
{
    gemm_body(A, Wm, bias, resid, rs4, rsb, out, kdim, flags, blockIdx.x*32);
}

// batched wi1: grid (128, 8); y = tau*2 + half
__global__ void __launch_bounds__(256) gemm_wi1(
    const float* __restrict__ h, const float* __restrict__ wi1,
    const float* __restrict__ bi1, float* __restrict__ A, float* __restrict__ Bm)
{
    int tau = blockIdx.y >> 1, half = blockIdx.y & 1;
    const float* Wm = wi1 + ((size_t)tau*256 + half*128)*128;
    const float* bias = half ? nullptr : (bi1 + tau*128);
    float* out = (half ? Bm : A) + (size_t)tau*ROWS*128;
    gemm_body(h, Wm, bias, nullptr, nullptr, nullptr, out, 128, 0, blockIdx.x*32);
}

// ---------------- HMMA fused inter kernel ----------------
// Block (b, tau). Per iteration: 2 senders -> M=128 rows (m = parity*64 + j).
// Xs = relu(A_i + B_j) bf16; x2 = Xs @ W2s^T via mma.sync; fp32 S-fragments
// persist in registers: S += w(i,j) * relu(x2 + bi2).
#define WSTR 68   // uint32 words per row (64 data + 4 pad)
#define SM_W2   0
#define SM_X    (SM_W2 + 128*WSTR*4)
#define SM_AS   (SM_X  + 128*WSTR*4)
#define SM_BS   (SM_AS + 64*WSTR*4)
#define SM_WB   (SM_BS + 64*WSTR*4)
#define SM_BI2  (SM_WB + 512)
#define SM_WSUM (SM_BI2 + 512)
#define SM_TOT  (SM_WSUM + 256)

__global__ void __launch_bounds__(256, 1) inter_hmma_kernel(
    const float* __restrict__ gA, const float* __restrict__ gB,
    const float* __restrict__ wi2, const float* __restrict__ bi2,
    const float* __restrict__ ep, const float* __restrict__ et,
    float* __restrict__ gS, float* __restrict__ gW)
{
    extern __shared__ char sm[];
    uint32_t* W2s = (uint32_t*)(sm + SM_W2);   // [n:128][k words:68] bf16x2
    uint32_t* Xs  = (uint32_t*)(sm + SM_X);    // [m:128][k words:68] bf16x2
    uint32_t* As  = (uint32_t*)(sm + SM_AS);   // [i:64][k words:68]
    uint32_t* Bs  = (uint32_t*)(sm + SM_BS);   // [j:64][k words:68]
    float* wbuf = (float*)(sm + SM_WB);        // [128]
    float* bi2s = (float*)(sm + SM_BI2);       // [128]
    float* wsum = (float*)(sm + SM_WSUM);      // [64]

    int tid = threadIdx.x, lane = tid & 31, wid = tid >> 5;
    int b = blockIdx.x, tau = blockIdx.y;
    int g = lane >> 2, q4 = lane & 3;
    int warp_m = wid >> 2;   // 0..1 (sender parity / m-half)
    int warp_n = wid & 3;    // 0..3 (n quarter)

    const float4* Ag = (const float4*)(gA + ((size_t)tau*ROWS + b*64)*128);
    const float4* Bg = (const float4*)(gB + ((size_t)tau*ROWS + b*64)*128);

    // prologue: convert A,B to bf16; transpose+convert W2
    for (int q = tid; q < 64*32; q += 256) {
        int r = q >> 5, w = q & 31;
        float4 a = Ag[r*32 + w];
        As[r*WSTR + w*2]     = pk2(a.x, a.y);
        As[r*WSTR + w*2 + 1] = pk2(a.z, a.w);
        float4 bb = Bg[r*32 + w];
        Bs[r*WSTR + w*2]     = pk2(bb.x, bb.y);
        Bs[r*WSTR + w*2 + 1] = pk2(bb.z, bb.w);
    }
    const float* w2g = wi2 + (size_t)tau*16384;
    for (int q = tid; q < 128*32; q += 256) {
        int n = q >> 5, w = q & 31;
        int k = w*4;
        float v0 = w2g[(size_t)(k+0)*128 + n];
        float v1 = w2g[(size_t)(k+1)*128 + n];
        float v2 = w2g[(size_t)(k+2)*128 + n];
        float v3 = w2g[(size_t)(k+3)*128 + n];
        W2s[n*WSTR + w*2]     = pk2(v0, v1);
        W2s[n*WSTR + w*2 + 1] = pk2(v2, v3);
    }
    if (tid < 128) bi2s[tid] = bi2[tau*128 + tid];
    if (tid < 64)  wsum[tid] = 0.f;
    __syncthreads();

    // per-thread bi2 for this warp's columns
    float bi2v[4][2];
    #pragma unroll
    for (int nt = 0; nt < 4; nt++) {
        int n0 = warp_n*32 + nt*8 + 2*q4;
        bi2v[nt][0] = bi2s[n0];
        bi2v[nt][1] = bi2s[n0 + 1];
    }

    float S[4][4][4] = {};
    const size_t ebase = (size_t)b*64*64;

    for (int it = 0; it < 32; it++) {
        int i0 = 2*it;
        // build Xs = relu(A_i + B_j), packed bf16
        {
            int m = tid >> 1, half = tid & 1;
            int ia = i0 + (m >> 6);
            int j  = m & 63;
            const uint32_t* Arow = As + ia*WSTR + half*32;
            const uint32_t* Brow = Bs + j *WSTR + half*32;
            uint32_t* Xrow = Xs + m*WSTR + half*32;
            #pragma unroll
            for (int w = 0; w < 8; w++) {
                uint4 av = *(const uint4*)&Arow[w*4];
                uint4 bv = *(const uint4*)&Brow[w*4];
                uint4 xv;
                xv.x = addrelu2(av.x, bv.x);
                xv.y = addrelu2(av.y, bv.y);
                xv.z = addrelu2(av.z, bv.z);
                xv.w = addrelu2(av.w, bv.w);
                *(uint4*)&Xrow[w*4] = xv;
            }
        }
        if (tid < 128) {
            int p = tid >> 6, j = tid & 63;
            size_t idx = ebase + (size_t)(i0 + p)*64 + j;
            wbuf[tid] = ep[idx] * et[idx*4 + tau];
        }
        __syncthreads();
        if (tid < 64) wsum[tid] += wbuf[tid] + wbuf[64 + tid];

        // x2 = Xs @ W2s^T  (M=128 x N=128 x K=128)
        float c[4][4][4] = {};
        #pragma unroll
        for (int kk = 0; kk < 8; kk++) {
            uint32_t a[4][4], bf[4][2];
            #pragma unroll
            for (int mt = 0; mt < 4; mt++) {
                int r0 = warp_m*64 + mt*16 + g;
                const uint32_t* base = Xs + r0*WSTR + kk*8 + q4;
                a[mt][0] = base[0];
                a[mt][1] = base[8*WSTR];
                a[mt][2] = base[4];
                a[mt][3] = base[8*WSTR + 4];
            }
            #pragma unroll
            for (int nt = 0; nt < 4; nt++) {
                int n0 = warp_n*32 + nt*8 + g;
                const uint32_t* base = W2s + n0*WSTR + kk*8 + q4;
                bf[nt][0] = base[0];
                bf[nt][1] = base[4];
            }
            #pragma unroll
            for (int mt = 0; mt < 4; mt++)
                #pragma unroll
                for (int nt = 0; nt < 4; nt++)
                    mma16816(c[mt][nt], a[mt], bf[nt]);
        }

        // epilogue: S += w * relu(x2 + bi2)
        #pragma unroll
        for (int mt = 0; mt < 4; mt++) {
            int m0 = warp_m*64 + mt*16 + g;
            float w0 = wbuf[m0], w1 = wbuf[m0 + 8];
            #pragma unroll
            for (int nt = 0; nt < 4; nt++) {
                S[mt][nt][0] += w0*fmaxf(c[mt][nt][0] + bi2v[nt][0], 0.f);
                S[mt][nt][1] += w0*fmaxf(c[mt][nt][1] + bi2v[nt][1], 0.f);
                S[mt][nt][2] += w1*fmaxf(c[mt][nt][2] + bi2v[nt][0], 0.f);
                S[mt][nt][3] += w1*fmaxf(c[mt][nt][3] + bi2v[nt][1], 0.f);
            }
        }
        __syncthreads();
    }

    // combine sender parities and write out
    float* Sout = (float*)(sm + SM_X);   // reuse Xs area: 64*132 floats
    __syncthreads();
    if (warp_m == 0) {
        #pragma unroll
        for (int mt = 0; mt < 4; mt++) {
            int j = mt*16 + g;
            #pragma unroll
            for (int nt = 0; nt < 4; nt++) {
                int n = warp_n*32 + nt*8 + 2*q4;
                *(float2*)&Sout[j*132 + n] =
                    make_float2(S[mt][nt][0], S[mt][nt][1]);
                *(float2*)&Sout[(j+8)*132 + n] =
                    make_float2(S[mt][nt][2], S[mt][nt][3]);
            }
        }
    }
    __syncthreads();
    if (warp_m == 1) {
        #pragma unroll
        for (int mt = 0; mt < 4; mt++) {
            int j = mt*16 + g;
            #pragma unroll
            for (int nt = 0; nt < 4; nt++) {
                int n = warp_n*32 + nt*8 + 2*q4;
                float2 v0 = *(float2*)&Sout[j*132 + n];
                v0.x += S[mt][nt][0]; v0.y += S[mt][nt][1];
                *(float2*)&Sout[j*132 + n] = v0;
                float2 v1 = *(float2*)&Sout[(j+8)*132 + n];
                v1.x += S[mt][nt][2]; v1.y += S[mt][nt][3];
                *(float2*)&Sout[(j+8)*132 + n] = v1;
            }
        }
    }
    __syncthreads();
    for (int q = tid; q < 64*32; q += 256) {
        int j = q >> 5, w = q & 31;
        float4 v = *(float4*)&Sout[j*132 + w*4];
        *(float4*)&gS[(size_t)(b*64 + j)*512 + tau*128 + w*4] = v;
    }
    if (tid < 64) gW[(size_t)(b*64 + tid)*4 + tau] = wsum[tid];
}

// ---------------- host orchestration ----------------
extern "C" void kernel_launch(void* const* d_in, const int* in_sizes, int n_in,
                              void* d_out, int out_size)
{
    const float* slots = (const float*)d_in[0];
    const float* ep    = (const float*)d_in[1];
    const float* et    = (const float*)d_in[2];
    const float* ls_g  = (const float*)d_in[3];
    const float* ls_b  = (const float*)d_in[4];
    const float* ws1   = (const float*)d_in[5];
    const float* bs1   = (const float*)d_in[6];
    const float* ws2   = (const float*)d_in[7];
    const float* bs2   = (const float*)d_in[8];
    const float* wi1   = (const float*)d_in[9];
    const float* bi1   = (const float*)d_in[10];
    const float* wi2   = (const float*)d_in[11];
    const float* bi2   = (const float*)d_in[12];
    const float* wi3   = (const float*)d_in[13];
    const float* bi3   = (const float*)d_in[14];
    const float* lu_g  = (const float*)d_in[15];
    const float* lu_b  = (const float*)d_in[16];
    const float* wu1   = (const float*)d_in[17];
    const float* bu1   = (const float*)d_in[18];
    const float* wu2   = (const float*)d_in[19];
    const float* bu2   = (const float*)d_in[20];
    float* out = (float*)d_out;

    float *XN, *T1, *HDS, *A, *Bm, *S, *W, *DI, *CN, *H;
    cudaGetSymbolAddress((void**)&XN,  g_XN);
    cudaGetSymbolAddress((void**)&T1,  g_T1);
    cudaGetSymbolAddress((void**)&HDS, g_HDS);
    cudaGetSymbolAddress((void**)&A,   g_A);
    cudaGetSymbolAddress((void**)&Bm,  g_Bm);
    cudaGetSymbolAddress((void**)&S,   g_S);
    cudaGetSymbolAddress((void**)&W,   g_W);
    cudaGetSymbolAddress((void**)&DI,  g_DI);
    cudaGetSymbolAddress((void**)&CN,  g_CN);
    cudaGetSymbolAddress((void**)&H,   g_H);

    cudaFuncSetAttribute(inter_hmma_kernel,
                         cudaFuncAttributeMaxDynamicSharedMemorySize, SM_TOT);

    const float* h = slots;
    for (int it = 0; it < 2; it++) {
        // delta_self path
        ln128_kernel<<<512, 256>>>(h, ls_g, ls_b, XN);
        gemm_n128<<<128, 256>>>(XN, ws1, bs1, nullptr, nullptr, nullptr,
                                T1, 128, RELU_FLAG);
        gemm_n128<<<128, 256>>>(T1, ws2, bs2, h, nullptr, nullptr,
                                HDS, 128, 0);

        // pair-layer-1 factorization, batched
        gemm_wi1<<<dim3(128, 8), 256>>>(h, wi1, bi1, A, Bm);

        // fused per-pair layer-2 + weighted sender reduction (HMMA)
        inter_hmma_kernel<<<dim3(BB, TT), 256, SM_TOT>>>(
            A, Bm, wi2, bi2, ep, et, S, W);

        // delta_inter = S[4096,512] @ wi3[512,128] (+ wsum*bi3 via RS4)
        gemm_n128<<<128, 256>>>(S, wi3, nullptr, nullptr, W, bi3,
                                DI, 512, RS4_FLAG);

        // update MLP
        ln256cat_kernel<<<512, 256>>>(HDS, DI, lu_g, lu_b, CN);
        gemm_n128<<<128, 256>>>(CN, wu1, bu1, nullptr, nullptr, nullptr,
                                T1, 256, RELU_FLAG);
        float* hnew = (it == 0) ? H : out;
        gemm_n128<<<128, 256>>>(T1, wu2, bu2, h, nullptr, nullptr,
                                hnew, 128, 0);
        h = H;
    }
}

// round 4
// speedup vs baseline: 8.1204x; 1.4741x over previous
#include <cuda_runtime.h>
#include <cuda_bf16.h>
#include <cstdint>

// Problem constants
#define BB 64
#define KK 64
#define DD 128
#define HH 128
#define TT 4
#define ROWS (BB*KK)        // 4096
#define EPSLN 1e-5f

#define RELU_FLAG  1
#define RS4_FLAG   4

// ---------------- scratch (no allocations allowed) ----------------
__device__ float g_HDS[ROWS*DD];
__device__ float g_DI [ROWS*DD];
__device__ float g_H  [ROWS*DD];
__device__ float g_W  [ROWS*TT];                 // [row][tau]
__device__ __nv_bfloat16 g_XNb[ROWS*DD];
__device__ __nv_bfloat16 g_Hb [ROWS*DD];
__device__ __nv_bfloat16 g_T1b[ROWS*DD];
__device__ __nv_bfloat16 g_CNb[ROWS*2*DD];
__device__ __nv_bfloat16 g_Ab [TT*ROWS*HH];
__device__ __nv_bfloat16 g_Bb [TT*ROWS*HH];
__device__ __nv_bfloat16 g_Sb [ROWS*TT*HH];      // [row][tau*128+n]

// ---------------- helpers ----------------
__device__ __forceinline__ uint32_t pk2(float lo, float hi){
    __nv_bfloat162 v = __floats2bfloat162_rn(lo, hi);
    return *(uint32_t*)&v;
}
__device__ __forceinline__ uint32_t addrelu2(uint32_t a, uint32_t b){
    __nv_bfloat162 av = *(__nv_bfloat162*)&a;
    __nv_bfloat162 bv = *(__nv_bfloat162*)&b;
    __nv_bfloat162 z  = __float2bfloat162_rn(0.f);
    __nv_bfloat162 r  = __hmax2(__hadd2(av, bv), z);
    return *(uint32_t*)&r;
}
__device__ __forceinline__ void mma16816(float c[4], const uint32_t a[4],
                                         uint32_t b0, uint32_t b1){
    asm volatile(
        "mma.sync.aligned.m16n8k16.row.col.f32.bf16.bf16.f32 "
        "{%0,%1,%2,%3}, {%4,%5,%6,%7}, {%8,%9}, {%0,%1,%2,%3};\n"
        : "+f"(c[0]), "+f"(c[1]), "+f"(c[2]), "+f"(c[3])
        : "r"(a[0]), "r"(a[1]), "r"(a[2]), "r"(a[3]), "r"(b0), "r"(b1));
}
__device__ __forceinline__ void ldmx4(uint32_t r[4], uint32_t a){
    asm volatile("ldmatrix.sync.aligned.m8n8.x4.shared.b16 {%0,%1,%2,%3}, [%4];"
        : "=r"(r[0]), "=r"(r[1]), "=r"(r[2]), "=r"(r[3]) : "r"(a));
}
__device__ __forceinline__ uint32_t s2u(const void* p){
    return (uint32_t)__cvta_generic_to_shared((void*)p);
}

// ---------------- LayerNorm, width 128: fp32 in -> bf16 LN out + bf16 h copy
__global__ void __launch_bounds__(256) ln128_kernel(
    const float* __restrict__ x, const float* __restrict__ g,
    const float* __restrict__ b, __nv_bfloat16* __restrict__ xnb,
    __nv_bfloat16* __restrict__ hb)
{
    int lane = threadIdx.x & 31;
    int wid  = threadIdx.x >> 5;
    int row  = blockIdx.x * 8 + wid;
    float4 v = ((const float4*)x)[row*32 + lane];
    float s = v.x + v.y + v.z + v.w;
    #pragma unroll
    for (int o = 16; o; o >>= 1) s += __shfl_xor_sync(0xffffffffu, s, o);
    float mu = s * (1.0f/128.0f);
    float dx = v.x-mu, dy = v.y-mu, dz = v.z-mu, dw = v.w-mu;
    float q = dx*dx + dy*dy + dz*dz + dw*dw;
    #pragma unroll
    for (int o = 16; o; o >>= 1) q += __shfl_xor_sync(0xffffffffu, q, o);
    float rs = rsqrtf(q * (1.0f/128.0f) + EPSLN);
    float4 gg = ((const float4*)g)[lane];
    float4 bb = ((const float4*)b)[lane];
    uint32_t* xw = (uint32_t*)(xnb + (size_t)row*128);
    xw[lane*2]   = pk2(dx*rs*gg.x + bb.x, dy*rs*gg.y + bb.y);
    xw[lane*2+1] = pk2(dz*rs*gg.z + bb.z, dw*rs*gg.w + bb.w);
    uint32_t* hw = (uint32_t*)(hb + (size_t)row*128);
    hw[lane*2]   = pk2(v.x, v.y);
    hw[lane*2+1] = pk2(v.z, v.w);
}

// ---------------- LayerNorm over concat([hds, di]) width 256 -> bf16 out ----
__global__ void __launch_bounds__(256) ln256cat_kernel(
    const float* __restrict__ hds, const float* __restrict__ di,
    const float* __restrict__ g, const float* __restrict__ b,
    __nv_bfloat16* __restrict__ out)
{
    int lane = threadIdx.x & 31;
    int wid  = threadIdx.x >> 5;
    int row  = blockIdx.x * 8 + wid;
    float4 v0 = ((const float4*)hds)[row*32 + lane];
    float4 v1 = ((const float4*)di )[row*32 + lane];
    float s = v0.x+v0.y+v0.z+v0.w + v1.x+v1.y+v1.z+v1.w;
    #pragma unroll
    for (int o = 16; o; o >>= 1) s += __shfl_xor_sync(0xffffffffu, s, o);
    float mu = s * (1.0f/256.0f);
    float a0=v0.x-mu, a1=v0.y-mu, a2=v0.z-mu, a3=v0.w-mu;
    float b0=v1.x-mu, b1=v1.y-mu, b2=v1.z-mu, b3=v1.w-mu;
    float q = a0*a0+a1*a1+a2*a2+a3*a3 + b0*b0+b1*b1+b2*b2+b3*b3;
    #pragma unroll
    for (int o = 16; o; o >>= 1) q += __shfl_xor_sync(0xffffffffu, q, o);
    float rs = rsqrtf(q * (1.0f/256.0f) + EPSLN);
    float4 g0 = ((const float4*)g)[lane];
    float4 g1 = ((const float4*)g)[32 + lane];
    float4 c0 = ((const float4*)b)[lane];
    float4 c1 = ((const float4*)b)[32 + lane];
    uint32_t* ow = (uint32_t*)(out + (size_t)row*256);
    ow[lane*2]      = pk2(a0*rs*g0.x + c0.x, a1*rs*g0.y + c0.y);
    ow[lane*2+1]    = pk2(a2*rs*g0.z + c0.z, a3*rs*g0.w + c0.w);
    ow[64+lane*2]   = pk2(b0*rs*g1.x + c1.x, b1*rs*g1.y + c1.y);
    ow[64+lane*2+1] = pk2(b2*rs*g1.z + c1.z, b3*rs*g1.w + c1.w);
}

// ---------------- HMMA GEMM: out[128 rows, 128] = Abf[·,K] @ Wf[K,128] ------
#define GSTR 36   // uint32 words per 64-col chunk row (32 data + 4 pad)

__device__ __forceinline__ void gemm_bf_body(
    const __nv_bfloat16* __restrict__ Abf, const float* __restrict__ Wf,
    const float* __restrict__ bias, const float* __restrict__ resid,
    const float* __restrict__ rs4, const float* __restrict__ rsb,
    float* __restrict__ outF, __nv_bfloat16* __restrict__ outB,
    int K, int flags, int rowBase)
{
    __shared__ uint32_t As[128*GSTR];
    __shared__ uint32_t Wt[128*GSTR];
    int tid = threadIdx.x, lane = tid & 31, wid = tid >> 5;
    int g = lane >> 2, q4 = lane & 3;
    int warp_m = wid >> 2, warp_n = wid & 3;
    int lA_row = lane & 15, lA_kw = (lane >> 4) << 2;
    int lB_row = (lane & 7) + ((lane >> 4) << 3);
    int lB_kw  = ((lane >> 3) & 1) << 2;
    uint32_t AsB = s2u(As), WtB = s2u(Wt);

    float c[4][4][4] = {};

    for (int kc = 0; kc < K; kc += 64) {
        #pragma unroll
        for (int l = 0; l < 4; l++) {
            int v = tid + l*256;
            int row = v >> 3, wq = v & 7;
            uint4 d = *(const uint4*)(Abf + (size_t)(rowBase+row)*K + kc + wq*8);
            *(uint4*)&As[row*GSTR + wq*4] = d;
        }
        #pragma unroll
        for (int l = 0; l < 4; l++) {
            int t = tid + l*256;
            int kw = t >> 5, ng = t & 31;
            float4 w0 = *(const float4*)(Wf + (size_t)(kc+2*kw)*128 + ng*4);
            float4 w1 = *(const float4*)(Wf + (size_t)(kc+2*kw+1)*128 + ng*4);
            Wt[(ng*4+0)*GSTR + kw] = pk2(w0.x, w1.x);
            Wt[(ng*4+1)*GSTR + kw] = pk2(w0.y, w1.y);
            Wt[(ng*4+2)*GSTR + kw] = pk2(w0.z, w1.z);
            Wt[(ng*4+3)*GSTR + kw] = pk2(w0.w, w1.w);
        }
        __syncthreads();
        #pragma unroll
        for (int kk = 0; kk < 4; kk++) {
            uint32_t wf0[4], wf1[4];
            ldmx4(wf0, WtB + ((warp_n*32 + lB_row)*GSTR + kk*8 + lB_kw)*4);
            ldmx4(wf1, WtB + ((warp_n*32 + 16 + lB_row)*GSTR + kk*8 + lB_kw)*4);
            #pragma unroll
            for (int mt = 0; mt < 4; mt++) {
                uint32_t a[4];
                ldmx4(a, AsB + ((warp_m*64 + mt*16 + lA_row)*GSTR + kk*8 + lA_kw)*4);
                mma16816(c[mt][0], a, wf0[0], wf0[1]);
                mma16816(c[mt][1], a, wf0[2], wf0[3]);
                mma16816(c[mt][2], a, wf1[0], wf1[1]);
                mma16816(c[mt][3], a, wf1[2], wf1[3]);
            }
        }
        __syncthreads();
    }

    // epilogue
    #pragma unroll
    for (int mt = 0; mt < 4; mt++) {
        int r0 = rowBase + warp_m*64 + mt*16 + g;
        int r1 = r0 + 8;
        float4 wa = make_float4(0,0,0,0), wb = make_float4(0,0,0,0);
        if (flags & RS4_FLAG) {
            wa = *(const float4*)&rs4[r0*4];
            wb = *(const float4*)&rs4[r1*4];
        }
        #pragma unroll
        for (int nt = 0; nt < 4; nt++) {
            int n0 = warp_n*32 + nt*8 + q4*2;
            float2 bv = bias ? *(const float2*)&bias[n0] : make_float2(0,0);
            float2 v0 = make_float2(c[mt][nt][0]+bv.x, c[mt][nt][1]+bv.y);
            float2 v1 = make_float2(c[mt][nt][2]+bv.x, c[mt][nt][3]+bv.y);
            if (flags & RS4_FLAG) {
                #pragma unroll
                for (int t = 0; t < 4; t++) {
                    float wta = (t==0)?wa.x:(t==1)?wa.y:(t==2)?wa.z:wa.w;
                    float wtb = (t==0)?wb.x:(t==1)?wb.y:(t==2)?wb.z:wb.w;
                    float2 rb = *(const float2*)&rsb[t*128 + n0];
                    v0.x += wta*rb.x; v0.y += wta*rb.y;
                    v1.x += wtb*rb.x; v1.y += wtb*rb.y;
                }
            }
            if (resid) {
                float2 h0 = *(const float2*)&resid[(size_t)r0*128 + n0];
                float2 h1 = *(const float2*)&resid[(size_t)r1*128 + n0];
                v0.x += h0.x; v0.y += h0.y; v1.x += h1.x; v1.y += h1.y;
            }
            if (flags & RELU_FLAG) {
                v0.x = fmaxf(v0.x,0.f); v0.y = fmaxf(v0.y,0.f);
                v1.x = fmaxf(v1.x,0.f); v1.y = fmaxf(v1.y,0.f);
            }
            if (outF) {
                *(float2*)&outF[(size_t)r0*128 + n0] = v0;
                *(float2*)&outF[(size_t)r1*128 + n0] = v1;
            }
            if (outB) {
                *(uint32_t*)&outB[(size_t)r0*128 + n0] = pk2(v0.x, v0.y);
                *(uint32_t*)&outB[(size_t)r1*128 + n0] = pk2(v1.x, v1.y);
            }
        }
    }
}

__global__ void __launch_bounds__(256) gemm_bf(
    const __nv_bfloat16* __restrict__ Abf, const float* __restrict__ Wf,
    const float* __restrict__ bias, const float* __restrict__ resid,
    const float* __restrict__ rs4, const float* __restrict__ rsb,
    float* outF, __nv_bfloat16* outB, int K, int flags)
{
    gemm_bf_body(Abf, Wf, bias, resid, rs4, rsb, outF, outB, K, flags,
                 blockIdx.x*128);
}

// batched wi1: grid (32, 8); y = tau*2 + half; outputs bf16 A/Bm
__global__ void __launch_bounds__(256) gemm_wi1(
    const __nv_bfloat16* __restrict__ hb, const float* __restrict__ wi1,
    const float* __restrict__ bi1, __nv_bfloat16* __restrict__ Ab,
    __nv_bfloat16* __restrict__ Bb)
{
    int tau = blockIdx.y >> 1, half = blockIdx.y & 1;
    const float* Wm = wi1 + ((size_t)tau*256 + half*128)*128;
    const float* bias = half ? nullptr : (bi1 + tau*128);
    __nv_bfloat16* outB = (half ? Bb : Ab) + (size_t)tau*ROWS*128;
    gemm_bf_body(hb, Wm, bias, nullptr, nullptr, nullptr, nullptr, outB,
                 128, 0, blockIdx.x*128);
}

// ---------------- HMMA fused inter kernel (sync-free main loop) -------------
// Block (b, tau). Warp (warp_m = sender parity, warp_n = n quarter).
// Per iteration it (senders i = 2it + warp_m):
//   X frag = relu(broadcast A[i] + ldmatrix(Bs rows j)); c = X @ W2^T frags;
//   S += Wmat[i][j] * relu(c + bi2).  No barriers inside the loop.
#define WSTR 68
#define SM_AS   0
#define SM_BS   17408
#define SM_W2   34816
#define SM_WM   69632
#define SM_BI2  86016
#define SM_WSUM 86528
#define SM_TOT  86784

__global__ void __launch_bounds__(256, 1) inter_hmma_kernel(
    const __nv_bfloat16* __restrict__ gAb, const __nv_bfloat16* __restrict__ gBb,
    const float* __restrict__ wi2, const float* __restrict__ bi2,
    const float* __restrict__ ep, const float* __restrict__ et,
    __nv_bfloat16* __restrict__ gSb, float* __restrict__ gW)
{
    extern __shared__ char sm[];
    uint32_t* Asm  = (uint32_t*)(sm + SM_AS);   // [i:64][WSTR]
    uint32_t* Bsm  = (uint32_t*)(sm + SM_BS);   // [j:64][WSTR]
    uint32_t* W2s  = (uint32_t*)(sm + SM_W2);   // [n:128][WSTR]
    float* Wmat = (float*)(sm + SM_WM);         // [i:64][j:64]
    float* bi2s = (float*)(sm + SM_BI2);        // [128]

    int tid = threadIdx.x, lane = tid & 31, wid = tid >> 5;
    int b = blockIdx.x, tau = blockIdx.y;
    int g = lane >> 2, q4 = lane & 3;
    int warp_m = wid >> 2;   // sender parity
    int warp_n = wid & 3;    // n quarter
    int lA_row = lane & 15, lA_kw = (lane >> 4) << 2;
    int lB_row = (lane & 7) + ((lane >> 4) << 3);
    int lB_kw  = ((lane >> 3) & 1) << 2;
    uint32_t BsB = s2u(sm) + SM_BS, W2B = s2u(sm) + SM_W2;

    // prologue: A/B bf16 tiles
    const uint4* Ag = (const uint4*)(gAb + ((size_t)tau*ROWS + b*64)*128);
    const uint4* Bg = (const uint4*)(gBb + ((size_t)tau*ROWS + b*64)*128);
    #pragma unroll
    for (int l = 0; l < 4; l++) {
        int v = tid + l*256;
        int row = v >> 4, wq = v & 15;
        *(uint4*)&Asm[row*WSTR + wq*4] = Ag[row*16 + wq];
        *(uint4*)&Bsm[row*WSTR + wq*4] = Bg[row*16 + wq];
    }
    // W2 transpose+convert: [k:128][n:128] fp32 -> [n][kword]
    const float* w2g = wi2 + (size_t)tau*16384;
    #pragma unroll
    for (int l = 0; l < 8; l++) {
        int t = tid + l*256;
        int kw = t >> 5, ng = t & 31;
        float4 w0 = *(const float4*)(w2g + (size_t)(2*kw)*128 + ng*4);
        float4 w1 = *(const float4*)(w2g + (size_t)(2*kw+1)*128 + ng*4);
        W2s[(ng*4+0)*WSTR + kw] = pk2(w0.x, w1.x);
        W2s[(ng*4+1)*WSTR + kw] = pk2(w0.y, w1.y);
        W2s[(ng*4+2)*WSTR + kw] = pk2(w0.z, w1.z);
        W2s[(ng*4+3)*WSTR + kw] = pk2(w0.w, w1.w);
    }
    // pair weights for all senders
    const size_t ebase = (size_t)b*64*64;
    #pragma unroll
    for (int l = 0; l < 16; l++) {
        int q = tid + l*256;
        Wmat[q] = ep[ebase + q] * et[(ebase + q)*4 + tau];
    }
    if (tid < 128) bi2s[tid] = bi2[tau*128 + tid];
    __syncthreads();

    // wsum writeout (independent of main loop)
    if (tid < 64) {
        float s = 0.f;
        #pragma unroll 8
        for (int i = 0; i < 64; i++) s += Wmat[i*64 + tid];
        gW[(size_t)(b*64 + tid)*4 + tau] = s;
    }

    float bi2v[4][2];
    #pragma unroll
    for (int nt = 0; nt < 4; nt++) {
        int n0 = warp_n*32 + nt*8 + 2*q4;
        bi2v[nt][0] = bi2s[n0];
        bi2v[nt][1] = bi2s[n0 + 1];
    }

    float S[4][4][4] = {};

    for (int it = 0; it < 32; it++) {
        int i = 2*it + warp_m;
        float c[4][4][4] = {};
        #pragma unroll
        for (int kk = 0; kk < 8; kk++) {
            uint32_t aw0 = Asm[i*WSTR + kk*8 + q4];
            uint32_t aw1 = Asm[i*WSTR + kk*8 + 4 + q4];
            uint32_t wf0[4], wf1[4];
            ldmx4(wf0, W2B + ((warp_n*32 + lB_row)*WSTR + kk*8 + lB_kw)*4);
            ldmx4(wf1, W2B + ((warp_n*32 + 16 + lB_row)*WSTR + kk*8 + lB_kw)*4);
            #pragma unroll
            for (int mt = 0; mt < 4; mt++) {
                uint32_t xb[4], x[4];
                ldmx4(xb, BsB + ((mt*16 + lA_row)*WSTR + kk*8 + lA_kw)*4);
                x[0] = addrelu2(xb[0], aw0);
                x[1] = addrelu2(xb[1], aw0);
                x[2] = addrelu2(xb[2], aw1);
                x[3] = addrelu2(xb[3], aw1);
                mma16816(c[mt][0], x, wf0[0], wf0[1]);
                mma16816(c[mt][1], x, wf0[2], wf0[3]);
                mma16816(c[mt][2], x, wf1[0], wf1[1]);
                mma16816(c[mt][3], x, wf1[2], wf1[3]);
            }
        }
        #pragma unroll
        for (int mt = 0; mt < 4; mt++) {
            float w0 = Wmat[i*64 + mt*16 + g];
            float w1 = Wmat[i*64 + mt*16 + g + 8];
            #pragma unroll
            for (int nt = 0; nt < 4; nt++) {
                S[mt][nt][0] += w0*fmaxf(c[mt][nt][0] + bi2v[nt][0], 0.f);
                S[mt][nt][1] += w0*fmaxf(c[mt][nt][1] + bi2v[nt][1], 0.f);
                S[mt][nt][2] += w1*fmaxf(c[mt][nt][2] + bi2v[nt][0], 0.f);
                S[mt][nt][3] += w1*fmaxf(c[mt][nt][3] + bi2v[nt][1], 0.f);
            }
        }
    }

    // combine sender parities through smem (reuse W2 area), write bf16 S
    float* Sout = (float*)(sm + SM_W2);   // 64*132 floats
    __syncthreads();
    if (warp_m == 0) {
        #pragma unroll
        for (int mt = 0; mt < 4; mt++) {
            int j = mt*16 + g;
            #pragma unroll
            for (int nt = 0; nt < 4; nt++) {
                int n = warp_n*32 + nt*8 + 2*q4;
                *(float2*)&Sout[j*132 + n] = make_float2(S[mt][nt][0], S[mt][nt][1]);
                *(float2*)&Sout[(j+8)*132 + n] = make_float2(S[mt][nt][2], S[mt][nt][3]);
            }
        }
    }
    __syncthreads();
    if (warp_m == 1) {
        #pragma unroll
        for (int mt = 0; mt < 4; mt++) {
            int j = mt*16 + g;
            #pragma unroll
            for (int nt = 0; nt < 4; nt++) {
                int n = warp_n*32 + nt*8 + 2*q4;
                float2 v0 = *(float2*)&Sout[j*132 + n];
                v0.x += S[mt][nt][0]; v0.y += S[mt][nt][1];
                *(float2*)&Sout[j*132 + n] = v0;
                float2 v1 = *(float2*)&Sout[(j+8)*132 + n];
                v1.x += S[mt][nt][2]; v1.y += S[mt][nt][3];
                *(float2*)&Sout[(j+8)*132 + n] = v1;
            }
        }
    }
    __syncthreads();
    for (int q = tid; q < 64*32; q += 256) {
        int j = q >> 5, w = q & 31;
        float4 v = *(float4*)&Sout[j*132 + w*4];
        uint2 u = make_uint2(pk2(v.x, v.y), pk2(v.z, v.w));
        *(uint2*)&gSb[(size_t)(b*64 + j)*512 + tau*128 + w*4] = u;
    }
}

// ---------------- host orchestration ----------------
extern "C" void kernel_launch(void* const* d_in, const int* in_sizes, int n_in,
                              void* d_out, int out_size)
{
    const float* slots = (const float*)d_in[0];
    const float* ep    = (const float*)d_in[1];
    const float* et    = (const float*)d_in[2];
    const float* ls_g  = (const float*)d_in[3];
    const float* ls_b  = (const float*)d_in[4];
    const float* ws1   = (const float*)d_in[5];
    const float* bs1   = (const float*)d_in[6];
    const float* ws2   = (const float*)d_in[7];
    const float* bs2   = (const float*)d_in[8];
    const float* wi1   = (const float*)d_in[9];
    const float* bi1   = (const float*)d_in[10];
    const float* wi2   = (const float*)d_in[11];
    const float* bi2   = (const float*)d_in[12];
    const float* wi3   = (const float*)d_in[13];
    const float* bi3   = (const float*)d_in[14];
    const float* lu_g  = (const float*)d_in[15];
    const float* lu_b  = (const float*)d_in[16];
    const float* wu1   = (const float*)d_in[17];
    const float* bu1   = (const float*)d_in[18];
    const float* wu2   = (const float*)d_in[19];
    const float* bu2   = (const float*)d_in[20];
    float* out = (float*)d_out;

    float *HDS, *DI, *H, *W;
    __nv_bfloat16 *XNb, *Hb, *T1b, *CNb, *Ab, *Bb, *Sb;
    cudaGetSymbolAddress((void**)&HDS, g_HDS);
    cudaGetSymbolAddress((void**)&DI,  g_DI);
    cudaGetSymbolAddress((void**)&H,   g_H);
    cudaGetSymbolAddress((void**)&W,   g_W);
    cudaGetSymbolAddress((void**)&XNb, g_XNb);
    cudaGetSymbolAddress((void**)&Hb,  g_Hb);
    cudaGetSymbolAddress((void**)&T1b, g_T1b);
    cudaGetSymbolAddress((void**)&CNb, g_CNb);
    cudaGetSymbolAddress((void**)&Ab,  g_Ab);
    cudaGetSymbolAddress((void**)&Bb,  g_Bb);
    cudaGetSymbolAddress((void**)&Sb,  g_Sb);

    cudaFuncSetAttribute(inter_hmma_kernel,
                         cudaFuncAttributeMaxDynamicSharedMemorySize, SM_TOT);

    const float* h = slots;
    for (int it = 0; it < 2; it++) {
        // delta_self path
        ln128_kernel<<<512, 256>>>(h, ls_g, ls_b, XNb, Hb);
        gemm_bf<<<32, 256>>>(XNb, ws1, bs1, nullptr, nullptr, nullptr,
                             nullptr, T1b, 128, RELU_FLAG);
        gemm_bf<<<32, 256>>>(T1b, ws2, bs2, h, nullptr, nullptr,
                             HDS, nullptr, 128, 0);

        // pair-layer-1 factorization, batched (bf16 out)
        gemm_wi1<<<dim3(32, 8), 256>>>(Hb, wi1, bi1, Ab, Bb);

        // fused per-pair layer-2 + weighted sender reduction (HMMA)
        inter_hmma_kernel<<<dim3(BB, TT), 256, SM_TOT>>>(
            Ab, Bb, wi2, bi2, ep, et, Sb, W);

        // delta_inter = Sb[4096,512] @ wi3[512,128] (+ wsum*bi3 via RS4)
        gemm_bf<<<32, 256>>>(Sb, wi3, nullptr, nullptr, W, bi3,
                             DI, nullptr, 512, RS4_FLAG);

        // update MLP
        ln256cat_kernel<<<512, 256>>>(HDS, DI, lu_g, lu_b, CNb);
        gemm_bf<<<32, 256>>>(CNb, wu1, bu1, nullptr, nullptr, nullptr,
                             nullptr, T1b, 256, RELU_FLAG);
        float* hnew = (it == 0) ? H : out;
        gemm_bf<<<32, 256>>>(T1b, wu2, bu2, h, nullptr, nullptr,
                             hnew, Hb, 128, 0);
        h = H;
    }
}

// round 5
// speedup vs baseline: 10.9303x; 1.3460x over previous
#include <cuda_runtime.h>
#include <cuda_bf16.h>
#include <cstdint>

// Problem constants
#define BB 64
#define KK 64
#define DD 128
#define HH 128
#define TT 4
#define ROWS (BB*KK)        // 4096
#define EPSLN 1e-5f

// ---------------- scratch (no allocations allowed) ----------------
__device__ float g_HDS[ROWS*DD];
__device__ float g_H  [ROWS*DD];
__device__ float g_W  [ROWS*TT];                 // [row][tau]
__device__ __nv_bfloat16 g_Ab [TT*ROWS*HH];
__device__ __nv_bfloat16 g_Bb [TT*ROWS*HH];
__device__ __nv_bfloat16 g_Sb [ROWS*TT*HH];      // [row][tau*128+n]

// prepped weights: bf16, [n][k-pair] chunked (4096 words per 64-k chunk)
#define W_WS1   0
#define W_WS2   8192
#define W_WU2   16384
#define W_WI3   24576
#define W_WU1   57344
#define W_WI1   73728
#define W_WI2F  139264
#define W_TOTAL 172032
__device__ __align__(16) uint32_t g_Wp[W_TOTAL];

// ---------------- helpers ----------------
__device__ __forceinline__ uint32_t pk2(float lo, float hi){
    __nv_bfloat162 v = __floats2bfloat162_rn(lo, hi);
    return *(uint32_t*)&v;
}
__device__ __forceinline__ uint32_t addrelu2(uint32_t a, uint32_t b){
    __nv_bfloat162 av = *(__nv_bfloat162*)&a;
    __nv_bfloat162 bv = *(__nv_bfloat162*)&b;
    __nv_bfloat162 z  = __float2bfloat162_rn(0.f);
    __nv_bfloat162 r  = __hmax2(__hadd2(av, bv), z);
    return *(uint32_t*)&r;
}
__device__ __forceinline__ void mma16816(float c[4], const uint32_t a[4],
                                         uint32_t b0, uint32_t b1){
    asm volatile(
        "mma.sync.aligned.m16n8k16.row.col.f32.bf16.bf16.f32 "
        "{%0,%1,%2,%3}, {%4,%5,%6,%7}, {%8,%9}, {%0,%1,%2,%3};\n"
        : "+f"(c[0]), "+f"(c[1]), "+f"(c[2]), "+f"(c[3])
        : "r"(a[0]), "r"(a[1]), "r"(a[2]), "r"(a[3]), "r"(b0), "r"(b1));
}
__device__ __forceinline__ void ldmx4(uint32_t r[4], uint32_t a){
    asm volatile("ldmatrix.sync.aligned.m8n8.x4.shared.b16 {%0,%1,%2,%3}, [%4];"
        : "=r"(r[0]), "=r"(r[1]), "=r"(r[2]), "=r"(r[3]) : "r"(a));
}
__device__ __forceinline__ uint32_t s2u(const void* p){
    return (uint32_t)__cvta_generic_to_shared((void*)p);
}

// ---------------- weight prep: fp32 [K][128] -> bf16 [chunk][n][kw] ---------
__global__ void __launch_bounds__(256) prep_weights(
    const float* __restrict__ ws1, const float* __restrict__ ws2,
    const float* __restrict__ wu2, const float* __restrict__ wi3,
    const float* __restrict__ wu1, const float* __restrict__ wi1,
    const float* __restrict__ wi2)
{
    int idx = blockIdx.x*256 + threadIdx.x;
    if (idx >= W_TOTAL) return;
    const float* src;
    int local;
    if (idx < W_WS2)       { src = ws1; local = idx - W_WS1; }
    else if (idx < W_WU2)  { src = ws2; local = idx - W_WS2; }
    else if (idx < W_WI3)  { src = wu2; local = idx - W_WU2; }
    else if (idx < W_WU1)  { src = wi3; local = idx - W_WI3; }
    else if (idx < W_WI1)  { src = wu1; local = idx - W_WU1; }
    else if (idx < W_WI2F) {
        int l = idx - W_WI1;
        int tau = l >> 14;               // 16384 words per tau
        src = wi1 + (size_t)tau*256*128;
        local = l & 16383;
    } else {
        // wi2 flat: [tau][n:128][w:64]
        int l = idx - W_WI2F;
        int tau = l >> 13;               // 8192 per tau
        int r = l & 8191;
        int n = r >> 6, w = r & 63;
        const float* s = wi2 + (size_t)tau*16384;
        g_Wp[idx] = pk2(s[(size_t)(2*w)*128 + n], s[(size_t)(2*w+1)*128 + n]);
        return;
    }
    int c = local >> 12;                 // 4096 words per chunk
    int r = local & 4095;
    int n = r >> 5, w = r & 31;
    int k = c*64 + 2*w;
    g_Wp[idx] = pk2(src[(size_t)k*128 + n], src[(size_t)(k+1)*128 + n]);
}

// ---------------- unit GEMM chunk (32 rows x 128 n x 64 k) ------------------
// 8 warps: warp_m = wid>>2 (row half of 16), warp_n = wid&3 (32 n each).
// c[nt][4] accumulates. Wt staged from prepped gmem each call.
#define GSTR 36

__device__ __forceinline__ void ug_chunk(
    float (&c)[4][4], char* sm, uint32_t smB, int wtOff,
    int aOff, int astr, int aChunkOff,
    const uint32_t* __restrict__ WgChunk, int tid)
{
    uint32_t* Wt = (uint32_t*)(sm + wtOff);
    #pragma unroll
    for (int l = 0; l < 4; l++) {
        int u = tid + l*256;             // uint4 index (1024)
        int n = u >> 3, w0 = (u & 7) * 4;
        *(uint4*)&Wt[n*GSTR + w0] = *(const uint4*)&WgChunk[u*4];
    }
    __syncthreads();
    int lane = tid & 31, wid = tid >> 5;
    int warp_m = wid >> 2, warp_n = wid & 3;
    int lA_row = lane & 15, lA_kw = (lane >> 4) << 2;
    int lB_row = (lane & 7) + ((lane >> 4) << 3);
    int lB_kw  = ((lane >> 3) & 1) << 2;
    uint32_t AsB = smB + aOff, WtB = smB + (uint32_t)wtOff;
    #pragma unroll
    for (int kk = 0; kk < 4; kk++) {
        uint32_t wf0[4], wf1[4], a[4];
        ldmx4(wf0, WtB + ((warp_n*32 + lB_row)*GSTR + kk*8 + lB_kw)*4);
        ldmx4(wf1, WtB + ((warp_n*32 + 16 + lB_row)*GSTR + kk*8 + lB_kw)*4);
        ldmx4(a, AsB + ((warp_m*16 + lA_row)*astr + aChunkOff + kk*8 + lA_kw)*4);
        mma16816(c[0], a, wf0[0], wf0[1]);
        mma16816(c[1], a, wf0[2], wf0[3]);
        mma16816(c[2], a, wf1[0], wf1[1]);
        mma16816(c[3], a, wf1[2], wf1[3]);
    }
    __syncthreads();
}

// ---------------- megaA: LN128 + self-MLP + wi1 (row-local) -----------------
// grid 128 x 32-row tiles.
#define MA_HS   0                       // 32*128 f32 = 16384
#define MA_XN   16384                   // 32*68*4 = 8704
#define MA_HB   25088                   // 8704
#define MA_T1   33792                   // 8704
#define MA_WT   42496                   // 128*36*4 = 18432
#define MA_TOT  60928

__global__ void __launch_bounds__(256) megaA_kernel(
    const float* __restrict__ h,
    const float* __restrict__ ls_g, const float* __restrict__ ls_b,
    const float* __restrict__ bs1, const float* __restrict__ bs2,
    const float* __restrict__ bi1,
    float* __restrict__ HDS, __nv_bfloat16* __restrict__ Ab,
    __nv_bfloat16* __restrict__ Bb)
{
    extern __shared__ char sm[];
    float* Hs = (float*)(sm + MA_HS);
    uint32_t* XN = (uint32_t*)(sm + MA_XN);
    uint32_t* HB = (uint32_t*)(sm + MA_HB);
    uint32_t* T1 = (uint32_t*)(sm + MA_T1);
    uint32_t smB = s2u(sm);
    int tid = threadIdx.x, lane = tid & 31, wid = tid >> 5;
    int rowBase = blockIdx.x * 32;
    int g = lane >> 2, q4 = lane & 3;
    int warp_m = wid >> 2, warp_n = wid & 3;
    int row0 = warp_m*16 + g, row1 = row0 + 8;

    // load h rows (fp32)
    #pragma unroll
    for (int l = 0; l < 4; l++) {
        int u = tid + l*256;             // float4 idx (1024)
        int r = u >> 5, q = u & 31;
        *(float4*)&Hs[r*128 + q*4] =
            *(const float4*)&h[(size_t)(rowBase+r)*128 + q*4];
    }
    __syncthreads();

    // LN128: warp per row, 4 passes; writes XN (LN out) + HB (raw h) bf16
    {
        float4 gg = ((const float4*)ls_g)[lane];
        float4 bb = ((const float4*)ls_b)[lane];
        #pragma unroll
        for (int p = 0; p < 4; p++) {
            int r = wid + p*8;
            float4 v = *(float4*)&Hs[r*128 + lane*4];
            float s = v.x + v.y + v.z + v.w;
            #pragma unroll
            for (int o = 16; o; o >>= 1) s += __shfl_xor_sync(0xffffffffu, s, o);
            float mu = s * (1.0f/128.0f);
            float dx = v.x-mu, dy = v.y-mu, dz = v.z-mu, dw = v.w-mu;
            float q = dx*dx + dy*dy + dz*dz + dw*dw;
            #pragma unroll
            for (int o = 16; o; o >>= 1) q += __shfl_xor_sync(0xffffffffu, q, o);
            float rs = rsqrtf(q * (1.0f/128.0f) + EPSLN);
            XN[r*68 + lane*2]   = pk2(dx*rs*gg.x + bb.x, dy*rs*gg.y + bb.y);
            XN[r*68 + lane*2+1] = pk2(dz*rs*gg.z + bb.z, dw*rs*gg.w + bb.w);
            HB[r*68 + lane*2]   = pk2(v.x, v.y);
            HB[r*68 + lane*2+1] = pk2(v.z, v.w);
        }
    }
    __syncthreads();

    // unit 1: T1 = relu(XN @ ws1 + bs1) -> smem bf16
    {
        float c[4][4] = {};
        ug_chunk(c, sm, smB, MA_WT, MA_XN, 68, 0,  g_Wp + W_WS1, tid);
        ug_chunk(c, sm, smB, MA_WT, MA_XN, 68, 32, g_Wp + W_WS1 + 4096, tid);
        #pragma unroll
        for (int nt = 0; nt < 4; nt++) {
            int n0 = warp_n*32 + nt*8 + 2*q4;
            float2 bv = *(const float2*)&bs1[n0];
            T1[row0*68 + (n0>>1)] =
                pk2(fmaxf(c[nt][0]+bv.x,0.f), fmaxf(c[nt][1]+bv.y,0.f));
            T1[row1*68 + (n0>>1)] =
                pk2(fmaxf(c[nt][2]+bv.x,0.f), fmaxf(c[nt][3]+bv.y,0.f));
        }
    }

    // unit 2: HDS = h + T1 @ ws2 + bs2 -> gmem fp32
    {
        float c[4][4] = {};
        ug_chunk(c, sm, smB, MA_WT, MA_T1, 68, 0,  g_Wp + W_WS2, tid);
        ug_chunk(c, sm, smB, MA_WT, MA_T1, 68, 32, g_Wp + W_WS2 + 4096, tid);
        #pragma unroll
        for (int nt = 0; nt < 4; nt++) {
            int n0 = warp_n*32 + nt*8 + 2*q4;
            float2 bv = *(const float2*)&bs2[n0];
            float2 h0 = *(float2*)&Hs[row0*128 + n0];
            float2 h1 = *(float2*)&Hs[row1*128 + n0];
            float2 v0 = make_float2(c[nt][0]+bv.x+h0.x, c[nt][1]+bv.y+h0.y);
            float2 v1 = make_float2(c[nt][2]+bv.x+h1.x, c[nt][3]+bv.y+h1.y);
            *(float2*)&HDS[(size_t)(rowBase+row0)*128 + n0] = v0;
            *(float2*)&HDS[(size_t)(rowBase+row1)*128 + n0] = v1;
        }
    }

    // units 3..10: A/B[tau] = HB @ wi1[tau,half] (+bi1 for half 0) -> gmem bf16
    #pragma unroll 1
    for (int u = 0; u < 8; u++) {
        int tau = u >> 1, half = u & 1;
        float c[4][4] = {};
        const uint32_t* Wg = g_Wp + W_WI1 + u*8192;
        ug_chunk(c, sm, smB, MA_WT, MA_HB, 68, 0,  Wg, tid);
        ug_chunk(c, sm, smB, MA_WT, MA_HB, 68, 32, Wg + 4096, tid);
        uint32_t* ob = (uint32_t*)((half ? Bb : Ab) +
                        ((size_t)tau*ROWS + rowBase)*128);
        #pragma unroll
        for (int nt = 0; nt < 4; nt++) {
            int n0 = warp_n*32 + nt*8 + 2*q4;
            float2 bv = half ? make_float2(0.f,0.f)
                             : *(const float2*)&bi1[tau*128 + n0];
            ob[row0*64 + (n0>>1)] = pk2(c[nt][0]+bv.x, c[nt][1]+bv.y);
            ob[row1*64 + (n0>>1)] = pk2(c[nt][2]+bv.x, c[nt][3]+bv.y);
        }
    }
}

// ---------------- HMMA fused inter kernel (sync-free main loop) -------------
#define WSTR 68
#define SM_AS   0
#define SM_BS   17408
#define SM_W2   34816
#define SM_WM   69632
#define SM_BI2  86016
#define SM_TOT  86784

__global__ void __launch_bounds__(256, 1) inter_hmma_kernel(
    const __nv_bfloat16* __restrict__ gAb, const __nv_bfloat16* __restrict__ gBb,
    const float* __restrict__ bi2,
    const float* __restrict__ ep, const float* __restrict__ et,
    __nv_bfloat16* __restrict__ gSb, float* __restrict__ gW)
{
    extern __shared__ char sm[];
    uint32_t* Asm  = (uint32_t*)(sm + SM_AS);
    uint32_t* Bsm  = (uint32_t*)(sm + SM_BS);
    uint32_t* W2s  = (uint32_t*)(sm + SM_W2);
    float* Wmat = (float*)(sm + SM_WM);
    float* bi2s = (float*)(sm + SM_BI2);

    int tid = threadIdx.x, lane = tid & 31, wid = tid >> 5;
    int b = blockIdx.x, tau = blockIdx.y;
    int g = lane >> 2, q4 = lane & 3;
    int warp_m = wid >> 2;
    int warp_n = wid & 3;
    int lA_row = lane & 15, lA_kw = (lane >> 4) << 2;
    int lB_row = (lane & 7) + ((lane >> 4) << 3);
    int lB_kw  = ((lane >> 3) & 1) << 2;
    uint32_t BsB = s2u(sm) + SM_BS, W2B = s2u(sm) + SM_W2;

    const uint4* Ag = (const uint4*)(gAb + ((size_t)tau*ROWS + b*64)*128);
    const uint4* Bg = (const uint4*)(gBb + ((size_t)tau*ROWS + b*64)*128);
    #pragma unroll
    for (int l = 0; l < 4; l++) {
        int v = tid + l*256;
        int row = v >> 4, wq = v & 15;
        *(uint4*)&Asm[row*WSTR + wq*4] = Ag[row*16 + wq];
        *(uint4*)&Bsm[row*WSTR + wq*4] = Bg[row*16 + wq];
    }
    // W2 from prepped flat layout
    {
        const uint4* src = (const uint4*)(g_Wp + W_WI2F + tau*8192);
        #pragma unroll
        for (int l = 0; l < 8; l++) {
            int u = tid + l*256;
            int n = u >> 4, q = u & 15;
            *(uint4*)&W2s[n*WSTR + q*4] = src[u];
        }
    }
    const size_t ebase = (size_t)b*64*64;
    #pragma unroll
    for (int l = 0; l < 16; l++) {
        int q = tid + l*256;
        Wmat[q] = ep[ebase + q] * et[(ebase + q)*4 + tau];
    }
    if (tid < 128) bi2s[tid] = bi2[tau*128 + tid];
    __syncthreads();

    if (tid < 64) {
        float s = 0.f;
        #pragma unroll 8
        for (int i = 0; i < 64; i++) s += Wmat[i*64 + tid];
        gW[(size_t)(b*64 + tid)*4 + tau] = s;
    }

    float bi2v[4][2];
    #pragma unroll
    for (int nt = 0; nt < 4; nt++) {
        int n0 = warp_n*32 + nt*8 + 2*q4;
        bi2v[nt][0] = bi2s[n0];
        bi2v[nt][1] = bi2s[n0 + 1];
    }

    float S[4][4][4] = {};

    for (int it = 0; it < 32; it++) {
        int i = 2*it + warp_m;
        float c[4][4][4] = {};
        #pragma unroll
        for (int kk = 0; kk < 8; kk++) {
            uint32_t aw0 = Asm[i*WSTR + kk*8 + q4];
            uint32_t aw1 = Asm[i*WSTR + kk*8 + 4 + q4];
            uint32_t wf0[4], wf1[4];
            ldmx4(wf0, W2B + ((warp_n*32 + lB_row)*WSTR + kk*8 + lB_kw)*4);
            ldmx4(wf1, W2B + ((warp_n*32 + 16 + lB_row)*WSTR + kk*8 + lB_kw)*4);
            #pragma unroll
            for (int mt = 0; mt < 4; mt++) {
                uint32_t xb[4], x[4];
                ldmx4(xb, BsB + ((mt*16 + lA_row)*WSTR + kk*8 + lA_kw)*4);
                x[0] = addrelu2(xb[0], aw0);
                x[1] = addrelu2(xb[1], aw0);
                x[2] = addrelu2(xb[2], aw1);
                x[3] = addrelu2(xb[3], aw1);
                mma16816(c[mt][0], x, wf0[0], wf0[1]);
                mma16816(c[mt][1], x, wf0[2], wf0[3]);
                mma16816(c[mt][2], x, wf1[0], wf1[1]);
                mma16816(c[mt][3], x, wf1[2], wf1[3]);
            }
        }
        #pragma unroll
        for (int mt = 0; mt < 4; mt++) {
            float w0 = Wmat[i*64 + mt*16 + g];
            float w1 = Wmat[i*64 + mt*16 + g + 8];
            #pragma unroll
            for (int nt = 0; nt < 4; nt++) {
                S[mt][nt][0] += w0*fmaxf(c[mt][nt][0] + bi2v[nt][0], 0.f);
                S[mt][nt][1] += w0*fmaxf(c[mt][nt][1] + bi2v[nt][1], 0.f);
                S[mt][nt][2] += w1*fmaxf(c[mt][nt][2] + bi2v[nt][0], 0.f);
                S[mt][nt][3] += w1*fmaxf(c[mt][nt][3] + bi2v[nt][1], 0.f);
            }
        }
    }

    float* Sout = (float*)(sm + SM_W2);
    __syncthreads();
    if (warp_m == 0) {
        #pragma unroll
        for (int mt = 0; mt < 4; mt++) {
            int j = mt*16 + g;
            #pragma unroll
            for (int nt = 0; nt < 4; nt++) {
                int n = warp_n*32 + nt*8 + 2*q4;
                *(float2*)&Sout[j*132 + n] = make_float2(S[mt][nt][0], S[mt][nt][1]);
                *(float2*)&Sout[(j+8)*132 + n] = make_float2(S[mt][nt][2], S[mt][nt][3]);
            }
        }
    }
    __syncthreads();
    if (warp_m == 1) {
        #pragma unroll
        for (int mt = 0; mt < 4; mt++) {
            int j = mt*16 + g;
            #pragma unroll
            for (int nt = 0; nt < 4; nt++) {
                int n = warp_n*32 + nt*8 + 2*q4;
                float2 v0 = *(float2*)&Sout[j*132 + n];
                v0.x += S[mt][nt][0]; v0.y += S[mt][nt][1];
                *(float2*)&Sout[j*132 + n] = v0;
                float2 v1 = *(float2*)&Sout[(j+8)*132 + n];
                v1.x += S[mt][nt][2]; v1.y += S[mt][nt][3];
                *(float2*)&Sout[(j+8)*132 + n] = v1;
            }
        }
    }
    __syncthreads();
    for (int q = tid; q < 64*32; q += 256) {
        int j = q >> 5, w = q & 31;
        float4 v = *(float4*)&Sout[j*132 + w*4];
        uint2 u = make_uint2(pk2(v.x, v.y), pk2(v.z, v.w));
        *(uint2*)&gSb[(size_t)(b*64 + j)*512 + tau*128 + w*4] = u;
    }
}

// ---------------- megaB: wi3 GEMM + LN256 + update MLP (row-local) ----------
#define MB_AS   0                       // 32*36*4 = 4608
#define MB_DI   4608                    // 32*132*4 = 16896
#define MB_CN   21504                   // 16896
#define MB_T1   38400                   // 32*68*4 = 8704
#define MB_WT   47104                   // 18432
#define MB_TOT  65536

__global__ void __launch_bounds__(256) megaB_kernel(
    const __nv_bfloat16* __restrict__ Sb, const float* __restrict__ Wq,
    const float* __restrict__ bi3, const float* __restrict__ HDS,
    const float* __restrict__ lu_g, const float* __restrict__ lu_b,
    const float* __restrict__ bu1, const float* __restrict__ bu2,
    const float* __restrict__ hResid, float* __restrict__ hOut)
{
    extern __shared__ char sm[];
    uint32_t* As = (uint32_t*)(sm + MB_AS);
    float*    DIs = (float*)(sm + MB_DI);
    uint32_t* CN = (uint32_t*)(sm + MB_CN);
    uint32_t* T1 = (uint32_t*)(sm + MB_T1);
    uint32_t smB = s2u(sm);
    int tid = threadIdx.x, lane = tid & 31, wid = tid >> 5;
    int rowBase = blockIdx.x * 32;
    int g = lane >> 2, q4 = lane & 3;
    int warp_m = wid >> 2, warp_n = wid & 3;
    int row0 = warp_m*16 + g, row1 = row0 + 8;

    // unit 1: DI = Sb @ wi3 (K=512) + wsum.bi3  -> smem fp32
    {
        float c[4][4] = {};
        for (int c8 = 0; c8 < 8; c8++) {
            // stage Sb chunk: rows 32, 64 k (32 words = 8 uint4 per row)
            int lr = tid >> 3, uu = tid & 7;
            *(uint4*)&As[lr*36 + uu*4] =
                *(const uint4*)&((const uint4*)Sb)[(size_t)(rowBase+lr)*64 + c8*8 + uu];
            ug_chunk(c, sm, smB, MB_WT, MB_AS, 36, 0,
                     g_Wp + W_WI3 + c8*4096, tid);
        }
        float4 wa = *(const float4*)&Wq[(size_t)(rowBase+row0)*4];
        float4 wb = *(const float4*)&Wq[(size_t)(rowBase+row1)*4];
        #pragma unroll
        for (int nt = 0; nt < 4; nt++) {
            int n0 = warp_n*32 + nt*8 + 2*q4;
            float2 v0 = make_float2(c[nt][0], c[nt][1]);
            float2 v1 = make_float2(c[nt][2], c[nt][3]);
            #pragma unroll
            for (int t = 0; t < 4; t++) {
                float wta = (t==0)?wa.x:(t==1)?wa.y:(t==2)?wa.z:wa.w;
                float wtb = (t==0)?wb.x:(t==1)?wb.y:(t==2)?wb.z:wb.w;
                float2 rb = *(const float2*)&bi3[t*128 + n0];
                v0.x += wta*rb.x; v0.y += wta*rb.y;
                v1.x += wtb*rb.x; v1.y += wtb*rb.y;
            }
            *(float2*)&DIs[row0*132 + n0] = v0;
            *(float2*)&DIs[row1*132 + n0] = v1;
        }
    }
    __syncthreads();

    // LN256 over [HDS row (gmem), DIs row (smem)] -> CN bf16 (stride 132 words)
    {
        float4 g0 = ((const float4*)lu_g)[lane];
        float4 g1 = ((const float4*)lu_g)[32 + lane];
        float4 c0 = ((const float4*)lu_b)[lane];
        float4 c1 = ((const float4*)lu_b)[32 + lane];
        #pragma unroll
        for (int p = 0; p < 4; p++) {
            int r = wid + p*8;
            float4 v0 = *(const float4*)&HDS[(size_t)(rowBase+r)*128 + lane*4];
            float4 v1 = *(float4*)&DIs[r*132 + lane*4];
            float s = v0.x+v0.y+v0.z+v0.w + v1.x+v1.y+v1.z+v1.w;
            #pragma unroll
            for (int o = 16; o; o >>= 1) s += __shfl_xor_sync(0xffffffffu, s, o);
            float mu = s * (1.0f/256.0f);
            float a0=v0.x-mu, a1=v0.y-mu, a2=v0.z-mu, a3=v0.w-mu;
            float b0=v1.x-mu, b1=v1.y-mu, b2=v1.z-mu, b3=v1.w-mu;
            float q = a0*a0+a1*a1+a2*a2+a3*a3 + b0*b0+b1*b1+b2*b2+b3*b3;
            #pragma unroll
            for (int o = 16; o; o >>= 1) q += __shfl_xor_sync(0xffffffffu, q, o);
            float rs = rsqrtf(q * (1.0f/256.0f) + EPSLN);
            CN[r*132 + lane*2]        = pk2(a0*rs*g0.x + c0.x, a1*rs*g0.y + c0.y);
            CN[r*132 + lane*2 + 1]    = pk2(a2*rs*g0.z + c0.z, a3*rs*g0.w + c0.w);
            CN[r*132 + 64 + lane*2]   = pk2(b0*rs*g1.x + c1.x, b1*rs*g1.y + c1.y);
            CN[r*132 + 64 + lane*2+1] = pk2(b2*rs*g1.z + c1.z, b3*rs*g1.w + c1.w);
        }
    }

    // unit 2: T1 = relu(CN @ wu1 + bu1)  (K=256)
    {
        float c[4][4] = {};
        for (int ch = 0; ch < 4; ch++)
            ug_chunk(c, sm, smB, MB_WT, MB_CN, 132, ch*32,
                     g_Wp + W_WU1 + ch*4096, tid);
        #pragma unroll
        for (int nt = 0; nt < 4; nt++) {
            int n0 = warp_n*32 + nt*8 + 2*q4;
            float2 bv = *(const float2*)&bu1[n0];
            T1[row0*68 + (n0>>1)] =
                pk2(fmaxf(c[nt][0]+bv.x,0.f), fmaxf(c[nt][1]+bv.y,0.f));
            T1[row1*68 + (n0>>1)] =
                pk2(fmaxf(c[nt][2]+bv.x,0.f), fmaxf(c[nt][3]+bv.y,0.f));
        }
    }

    // unit 3: hOut = hResid + T1 @ wu2 + bu2  -> gmem fp32
    {
        float c[4][4] = {};
        ug_chunk(c, sm, smB, MB_WT, MB_T1, 68, 0,  g_Wp + W_WU2, tid);
        ug_chunk(c, sm, smB, MB_WT, MB_T1, 68, 32, g_Wp + W_WU2 + 4096, tid);
        #pragma unroll
        for (int nt = 0; nt < 4; nt++) {
            int n0 = warp_n*32 + nt*8 + 2*q4;
            float2 bv = *(const float2*)&bu2[n0];
            float2 h0 = *(const float2*)&hResid[(size_t)(rowBase+row0)*128 + n0];
            float2 h1 = *(const float2*)&hResid[(size_t)(rowBase+row1)*128 + n0];
            *(float2*)&hOut[(size_t)(rowBase+row0)*128 + n0] =
                make_float2(c[nt][0]+bv.x+h0.x, c[nt][1]+bv.y+h0.y);
            *(float2*)&hOut[(size_t)(rowBase+row1)*128 + n0] =
                make_float2(c[nt][2]+bv.x+h1.x, c[nt][3]+bv.y+h1.y);
        }
    }
}

// ---------------- host orchestration ----------------
extern "C" void kernel_launch(void* const* d_in, const int* in_sizes, int n_in,
                              void* d_out, int out_size)
{
    const float* slots = (const float*)d_in[0];
    const float* ep    = (const float*)d_in[1];
    const float* et    = (const float*)d_in[2];
    const float* ls_g  = (const float*)d_in[3];
    const float* ls_b  = (const float*)d_in[4];
    const float* ws1   = (const float*)d_in[5];
    const float* bs1   = (const float*)d_in[6];
    const float* ws2   = (const float*)d_in[7];
    const float* bs2   = (const float*)d_in[8];
    const float* wi1   = (const float*)d_in[9];
    const float* bi1   = (const float*)d_in[10];
    const float* wi2   = (const float*)d_in[11];
    const float* bi2   = (const float*)d_in[12];
    const float* wi3   = (const float*)d_in[13];
    const float* bi3   = (const float*)d_in[14];
    const float* lu_g  = (const float*)d_in[15];
    const float* lu_b  = (const float*)d_in[16];
    const float* wu1   = (const float*)d_in[17];
    const float* bu1   = (const float*)d_in[18];
    const float* wu2   = (const float*)d_in[19];
    const float* bu2   = (const float*)d_in[20];
    float* out = (float*)d_out;

    float *HDS, *H, *W;
    __nv_bfloat16 *Ab, *Bb, *Sb;
    cudaGetSymbolAddress((void**)&HDS, g_HDS);
    cudaGetSymbolAddress((void**)&H,   g_H);
    cudaGetSymbolAddress((void**)&W,   g_W);
    cudaGetSymbolAddress((void**)&Ab,  g_Ab);
    cudaGetSymbolAddress((void**)&Bb,  g_Bb);
    cudaGetSymbolAddress((void**)&Sb,  g_Sb);

    cudaFuncSetAttribute(megaA_kernel,
        cudaFuncAttributeMaxDynamicSharedMemorySize, MA_TOT);
    cudaFuncSetAttribute(megaB_kernel,
        cudaFuncAttributeMaxDynamicSharedMemorySize, MB_TOT);
    cudaFuncSetAttribute(inter_hmma_kernel,
        cudaFuncAttributeMaxDynamicSharedMemorySize, SM_TOT);

    prep_weights<<<(W_TOTAL+255)/256, 256>>>(ws1, ws2, wu2, wi3, wu1, wi1, wi2);

    const float* h = slots;
    for (int it = 0; it < 2; it++) {
        megaA_kernel<<<128, 256, MA_TOT>>>(h, ls_g, ls_b, bs1, bs2, bi1,
                                           HDS, Ab, Bb);
        inter_hmma_kernel<<<dim3(BB, TT), 256, SM_TOT>>>(
            Ab, Bb, bi2, ep, et, Sb, W);
        float* hnew = (it == 0) ? H : out;
        megaB_kernel<<<128, 256, MB_TOT>>>(Sb, W, bi3, HDS, lu_g, lu_b,
                                           bu1, bu2, h, hnew);
        h = H;
    }
}